// round 12
// baseline (speedup 1.0000x reference)
#include <cuda_runtime.h>
#include <cuda_bf16.h>
#include <cstdint>

// Shapes (fixed per reference setup_inputs)
#define B    32
#define C    768
#define CR   192
#define HW   1024          // 32*32
#define ROWS (B * C)       // 24576 (b,c) rows of 1024 floats each
#define NB   296           // persistent grid: 2 blocks/SM x 148 SMs (co-resident)
#define NW   (NB * 8)      // total warps = 2368

// Scratch (no device allocation allowed in kernel_launch)
__device__ float g_s[B * C];    // squeezed means   [B, C]
__device__ float g_h[B * CR];   // hidden (swish)   [B, Cr]
__device__ float g_g[B * C];    // gate (sigmoid)   [B, C]

// Grid barrier state. bar_gen increments monotonically across barriers and
// graph replays; bar_count returns to 0 at each release -> replay-safe.
__device__ unsigned int g_bar_count = 0;
__device__ unsigned int g_bar_gen   = 0;

__device__ __forceinline__ void grid_sync() {
    __threadfence();          // make this block's phase writes globally visible
    __syncthreads();
    if (threadIdx.x == 0) {
        volatile unsigned int* genp = &g_bar_gen;
        unsigned int gen = *genp;
        if (atomicAdd(&g_bar_count, 1u) == NB - 1) {
            g_bar_count = 0;          // safe: all NB arrived, none can re-arrive
            __threadfence();          // count reset ordered before gen bump
            *genp = gen + 1;
        } else {
            while (*genp == gen) __nanosleep(64);
        }
    }
    __syncthreads();
}

// 256-bit read-only load with L2 evict-last priority (ptxas/sm_103 requires
// .v8.b32 for .L2::evict_last). Pins x in L2 for the phase-D re-read.
struct f8 { float v[8]; };
__device__ __forceinline__ f8 ld_f8_evict_last(const void* p) {
    uint32_t a, b, c, d, e, f, g, h;
    asm("ld.global.nc.L2::evict_last.v8.b32 {%0,%1,%2,%3,%4,%5,%6,%7}, [%8];"
        : "=r"(a), "=r"(b), "=r"(c), "=r"(d),
          "=r"(e), "=r"(f), "=r"(g), "=r"(h) : "l"(p));
    f8 r;
    r.v[0] = __uint_as_float(a); r.v[1] = __uint_as_float(b);
    r.v[2] = __uint_as_float(c); r.v[3] = __uint_as_float(d);
    r.v[4] = __uint_as_float(e); r.v[5] = __uint_as_float(f);
    r.v[6] = __uint_as_float(g); r.v[7] = __uint_as_float(h);
    return r;
}

// ---------------------------------------------------------------------------
// One persistent kernel, 4 phases split by grid barriers. Removes two graph
// node boundaries (~12-14us of measured inter-kernel gap on this bench).
// ---------------------------------------------------------------------------
__global__ __launch_bounds__(256, 2) void se_fused_kernel(
    const float* __restrict__ x,
    const float* __restrict__ w1, const float* __restrict__ b1,
    const float* __restrict__ w2, const float* __restrict__ b2,
    float* __restrict__ out)
{
    const int tid  = threadIdx.x;
    const int warp = tid >> 5;
    const int lane = tid & 31;
    const int gw   = blockIdx.x * 8 + warp;       // global warp id < NW

    // ---- Phase A: global average pool (warp per row, evict-last pins x) ----
    for (int row = gw; row < ROWS; row += NW) {
        const float* p = x + (size_t)row * HW;    // 4096B row = 128 x 32B
        float acc = 0.0f;
#pragma unroll
        for (int i = 0; i < 4; ++i) {
            f8 v = ld_f8_evict_last(p + (lane + i * 32) * 8);
            acc += ((v.v[0] + v.v[1]) + (v.v[2] + v.v[3]))
                 + ((v.v[4] + v.v[5]) + (v.v[6] + v.v[7]));
        }
#pragma unroll
        for (int o = 16; o > 0; o >>= 1)
            acc += __shfl_xor_sync(0xffffffffu, acc, o);
        if (lane == 0)
            g_s[row] = acc * (1.0f / (float)HW);
    }
    grid_sync();

    // ---- Phase B: h = swish(s @ w1^T + b1)  (warp per output, 6144 outs) ----
    for (int o = gw; o < B * CR; o += NW) {
        const int b = o / CR;
        const int j = o % CR;
        const float4* wr = reinterpret_cast<const float4*>(w1 + (size_t)j * C);
        const float4* sv = reinterpret_cast<const float4*>(g_s + (size_t)b * C);
        float a = 0.0f;
#pragma unroll
        for (int i = 0; i < 6; ++i) {             // 6*32 f4 = 768 floats
            float4 w = wr[lane + i * 32];
            float4 s = sv[lane + i * 32];
            a += w.x * s.x + w.y * s.y + w.z * s.z + w.w * s.w;
        }
#pragma unroll
        for (int off = 16; off > 0; off >>= 1)
            a += __shfl_xor_sync(0xffffffffu, a, off);
        if (lane == 0) {
            a += b1[j];
            g_h[o] = a * (1.0f / (1.0f + __expf(-a)));   // swish
        }
    }
    grid_sync();

    // ---- Phase C: g = sigmoid(h @ w2^T + b2)  (warp per output, 24576) ----
    for (int o = gw; o < ROWS; o += NW) {
        const int b = o / C;
        const int c = o % C;
        const float2* wr = reinterpret_cast<const float2*>(w2 + (size_t)c * CR);
        const float2* hv = reinterpret_cast<const float2*>(g_h + (size_t)b * CR);
        float a = 0.0f;
#pragma unroll
        for (int i = 0; i < 3; ++i) {             // 3*32 f2 = 192 floats
            float2 w = wr[lane + i * 32];
            float2 h = hv[lane + i * 32];
            a += w.x * h.x + w.y * h.y;
        }
#pragma unroll
        for (int off = 16; off > 0; off >>= 1)
            a += __shfl_xor_sync(0xffffffffu, a, off);
        if (lane == 0)
            g_g[o] = 1.0f / (1.0f + __expf(-(a + b2[c])));
    }
    grid_sync();

    // ---- Phase D: stream scale, 8 rows per block-iter (MLP=8). x reads hit
    // the evict-last-pinned L2 copy; stores are evict-first (__stcs). ----
    for (int r0 = blockIdx.x * 8; r0 < ROWS; r0 += NB * 8) {
        const float4* xp = reinterpret_cast<const float4*>(x) + (size_t)r0 * 256;
        float4*       op = reinterpret_cast<float4*>(out)     + (size_t)r0 * 256;
        float gv[8];
#pragma unroll
        for (int i = 0; i < 8; ++i) gv[i] = __ldg(&g_g[r0 + i]);
#pragma unroll
        for (int i = 0; i < 8; ++i) {
            float4 v = xp[tid + i * 256];
            v.x *= gv[i]; v.y *= gv[i]; v.z *= gv[i]; v.w *= gv[i];
            __stcs(op + tid + i * 256, v);
        }
    }
}

// ---------------------------------------------------------------------------
extern "C" void kernel_launch(void* const* d_in, const int* in_sizes, int n_in,
                              void* d_out, int out_size) {
    const float* x  = (const float*)d_in[0];   // [B, C, H, W]
    const float* w1 = (const float*)d_in[1];   // [Cr, C]
    const float* b1 = (const float*)d_in[2];   // [Cr]
    const float* w2 = (const float*)d_in[3];   // [C, Cr]
    const float* b2 = (const float*)d_in[4];   // [C]
    float* out = (float*)d_out;

    se_fused_kernel<<<NB, 256>>>(x, w1, b1, w2, b2, out);
}

// round 13
// speedup vs baseline: 1.4979x; 1.4979x over previous
#include <cuda_runtime.h>
#include <cuda_bf16.h>
#include <cstdint>

// Shapes (fixed per reference setup_inputs)
#define B    32
#define C    768
#define CR   192
#define HW   1024          // 32*32
#define ROWS (B * C)       // 24576 (b,c) rows of 1024 floats each

// Persistent grid: 8 blocks/SM x 148 SMs. __launch_bounds__(256, 8) forces
// regs <= 32 and smem is 0, so all 1184 blocks are guaranteed co-resident
// (64 warps/SM = full occupancy) -> grid barrier is deadlock-free.
#define NB   1184
#define NW   (NB * 8)      // total warps = 9472

// Scratch (no device allocation allowed in kernel_launch)
__device__ float g_s[B * C];    // squeezed means   [B, C]
__device__ float g_h[B * CR];   // hidden (swish)   [B, Cr]
__device__ float g_g[B * C];    // gate (sigmoid)   [B, C]

// Grid barrier state. gen increments monotonically across barriers and graph
// replays; count returns to 0 at each release -> replay-safe.
__device__ unsigned int g_bar_count = 0;
__device__ unsigned int g_bar_gen   = 0;

__device__ __forceinline__ void grid_sync() {
    __threadfence();          // make this block's phase writes globally visible
    __syncthreads();
    if (threadIdx.x == 0) {
        volatile unsigned int* genp = &g_bar_gen;
        unsigned int gen = *genp;
        if (atomicAdd(&g_bar_count, 1u) == NB - 1) {
            g_bar_count = 0;          // safe: all NB arrived, none can re-arrive
            __threadfence();          // count reset ordered before gen bump
            *genp = gen + 1;
        } else {
            while (*genp == gen) __nanosleep(64);
        }
    }
    __syncthreads();
}

// 256-bit read-only load with L2 evict-last priority (ptxas/sm_103 requires
// .v8.b32 for .L2::evict_last). Pins x in L2 for the phase-D re-read.
struct f8 { float v[8]; };
__device__ __forceinline__ f8 ld_f8_evict_last(const void* p) {
    uint32_t a, b, c, d, e, f, g, h;
    asm("ld.global.nc.L2::evict_last.v8.b32 {%0,%1,%2,%3,%4,%5,%6,%7}, [%8];"
        : "=r"(a), "=r"(b), "=r"(c), "=r"(d),
          "=r"(e), "=r"(f), "=r"(g), "=r"(h) : "l"(p));
    f8 r;
    r.v[0] = __uint_as_float(a); r.v[1] = __uint_as_float(b);
    r.v[2] = __uint_as_float(c); r.v[3] = __uint_as_float(d);
    r.v[4] = __uint_as_float(e); r.v[5] = __uint_as_float(f);
    r.v[6] = __uint_as_float(g); r.v[7] = __uint_as_float(h);
    return r;
}

// ---------------------------------------------------------------------------
// One persistent kernel at FULL occupancy, 4 phases split by grid barriers.
// Removes two graph node boundaries while keeping the per-phase warp
// parallelism of the 3-kernel version (R12's 2-blocks/SM starved HBM).
// ---------------------------------------------------------------------------
__global__ __launch_bounds__(256, 8) void se_fused_kernel(
    const float* __restrict__ x,
    const float* __restrict__ w1, const float* __restrict__ b1,
    const float* __restrict__ w2, const float* __restrict__ b2,
    float* __restrict__ out)
{
    const int tid  = threadIdx.x;
    const int warp = tid >> 5;
    const int lane = tid & 31;
    const int gw   = blockIdx.x * 8 + warp;       // global warp id < NW

    // ---- Phase A: global average pool (warp per row, evict-last pins x) ----
    for (int row = gw; row < ROWS; row += NW) {
        const float* p = x + (size_t)row * HW;    // 4096B row = 128 x 32B
        float acc = 0.0f;
#pragma unroll
        for (int i = 0; i < 4; ++i) {
            f8 v = ld_f8_evict_last(p + (lane + i * 32) * 8);
            acc += ((v.v[0] + v.v[1]) + (v.v[2] + v.v[3]))
                 + ((v.v[4] + v.v[5]) + (v.v[6] + v.v[7]));
        }
#pragma unroll
        for (int o = 16; o > 0; o >>= 1)
            acc += __shfl_xor_sync(0xffffffffu, acc, o);
        if (lane == 0)
            g_s[row] = acc * (1.0f / (float)HW);
    }
    grid_sync();

    // ---- Phase B: h = swish(s @ w1^T + b1)  (warp per output, 6144 outs) ----
    for (int o = gw; o < B * CR; o += NW) {
        const int b = o / CR;
        const int j = o % CR;
        const float4* wr = reinterpret_cast<const float4*>(w1 + (size_t)j * C);
        const float4* sv = reinterpret_cast<const float4*>(g_s + (size_t)b * C);
        float a = 0.0f;
#pragma unroll
        for (int i = 0; i < 6; ++i) {             // 6*32 f4 = 768 floats
            float4 w = wr[lane + i * 32];
            float4 s = sv[lane + i * 32];
            a += w.x * s.x + w.y * s.y + w.z * s.z + w.w * s.w;
        }
#pragma unroll
        for (int off = 16; off > 0; off >>= 1)
            a += __shfl_xor_sync(0xffffffffu, a, off);
        if (lane == 0) {
            a += b1[j];
            g_h[o] = a * (1.0f / (1.0f + __expf(-a)));   // swish
        }
    }
    grid_sync();

    // ---- Phase C: g = sigmoid(h @ w2^T + b2)  (warp per output, 24576) ----
    for (int o = gw; o < ROWS; o += NW) {
        const int b = o / C;
        const int c = o % C;
        const float2* wr = reinterpret_cast<const float2*>(w2 + (size_t)c * CR);
        const float2* hv = reinterpret_cast<const float2*>(g_h + (size_t)b * CR);
        float a = 0.0f;
#pragma unroll
        for (int i = 0; i < 3; ++i) {             // 3*32 f2 = 192 floats
            float2 w = wr[lane + i * 32];
            float2 h = hv[lane + i * 32];
            a += w.x * h.x + w.y * h.y;
        }
#pragma unroll
        for (int off = 16; off > 0; off >>= 1)
            a += __shfl_xor_sync(0xffffffffu, a, off);
        if (lane == 0)
            g_g[o] = 1.0f / (1.0f + __expf(-(a + b2[c])));
    }
    grid_sync();

    // ---- Phase D: stream scale, 4 rows per block-iter (MLP=4, low regs).
    // x reads hit the evict-last-pinned L2 copy; stores are evict-first. ----
    for (int r0 = blockIdx.x * 4; r0 < ROWS; r0 += NB * 4) {
        const float4* xp = reinterpret_cast<const float4*>(x) + (size_t)r0 * 256;
        float4*       op = reinterpret_cast<float4*>(out)     + (size_t)r0 * 256;
        const float gv0 = g_g[r0 + 0];
        const float gv1 = g_g[r0 + 1];
        const float gv2 = g_g[r0 + 2];
        const float gv3 = g_g[r0 + 3];

        float4 v0 = xp[tid];
        float4 v1 = xp[tid + 256];
        float4 v2 = xp[tid + 512];
        float4 v3 = xp[tid + 768];

        v0.x *= gv0; v0.y *= gv0; v0.z *= gv0; v0.w *= gv0;
        v1.x *= gv1; v1.y *= gv1; v1.z *= gv1; v1.w *= gv1;
        v2.x *= gv2; v2.y *= gv2; v2.z *= gv2; v2.w *= gv2;
        v3.x *= gv3; v3.y *= gv3; v3.z *= gv3; v3.w *= gv3;

        __stcs(op + tid,       v0);
        __stcs(op + tid + 256, v1);
        __stcs(op + tid + 512, v2);
        __stcs(op + tid + 768, v3);
    }
}

// ---------------------------------------------------------------------------
extern "C" void kernel_launch(void* const* d_in, const int* in_sizes, int n_in,
                              void* d_out, int out_size) {
    const float* x  = (const float*)d_in[0];   // [B, C, H, W]
    const float* w1 = (const float*)d_in[1];   // [Cr, C]
    const float* b1 = (const float*)d_in[2];   // [Cr]
    const float* w2 = (const float*)d_in[3];   // [C, Cr]
    const float* b2 = (const float*)d_in[4];   // [C]
    float* out = (float*)d_out;

    se_fused_kernel<<<NB, 256>>>(x, w1, b1, w2, b2, out);
}

// round 14
// speedup vs baseline: 1.6682x; 1.1137x over previous
#include <cuda_runtime.h>
#include <cuda_bf16.h>
#include <cstdint>

// Shapes (fixed per reference setup_inputs)
#define B    32
#define C    768
#define CR   192
#define HW   1024          // 32*32
#define ROWS (B * C)       // 24576 (b,c) rows of 1024 floats each

// 1184 = 148 SMs x 8 blocks (32 regs, 0 static smem -> all co-resident).
// Organized as 32 independent batch-groups of 37 blocks each.
#define NB     1184
#define GRP    37          // blocks per batch group
#define GW     (GRP * 8)   // warps per group = 296
#define DCHUNK 21          // ceil(768/37) rows per block in the scale phase

// Scratch (no device allocation allowed in kernel_launch)
__device__ float g_s[B * C];    // squeezed means   [B, C]
__device__ float g_h[B * CR];   // hidden (swish)   [B, Cr]
__device__ float g_g[B * C];    // gate (sigmoid)   [B, C]

// Per-batch barrier state, padded to 128B per batch to avoid L2 atomic-line
// contention between groups. gen is monotonic across barriers and replays;
// count returns to 0 at each release -> replay-safe.
__device__ unsigned int g_cnt[B * 32];
__device__ unsigned int g_gen[B * 32];

__device__ __forceinline__ void batch_sync(int b) {
    __threadfence();          // group's phase writes visible before arrive
    __syncthreads();
    if (threadIdx.x == 0) {
        volatile unsigned int* genp = &g_gen[b * 32];
        unsigned int gen = *genp;
        if (atomicAdd(&g_cnt[b * 32], 1u) == GRP - 1) {
            g_cnt[b * 32] = 0;        // all GRP arrived; none can re-arrive
            __threadfence();
            *genp = gen + 1;
        } else {
            while (*genp == gen) __nanosleep(32);
        }
    }
    __syncthreads();
    __threadfence();          // acquire: other blocks' writes now readable
}

// 256-bit read-only load with L2 evict-last priority (ptxas/sm_103 requires
// .v8.b32 for .L2::evict_last). Keeps this batch's x slice L2-resident for
// the scale phase a few microseconds later.
struct f8 { float v[8]; };
__device__ __forceinline__ f8 ld_f8_evict_last(const void* p) {
    uint32_t a, b, c, d, e, f, g, h;
    asm("ld.global.nc.L2::evict_last.v8.b32 {%0,%1,%2,%3,%4,%5,%6,%7}, [%8];"
        : "=r"(a), "=r"(b), "=r"(c), "=r"(d),
          "=r"(e), "=r"(f), "=r"(g), "=r"(h) : "l"(p));
    f8 r;
    r.v[0] = __uint_as_float(a); r.v[1] = __uint_as_float(b);
    r.v[2] = __uint_as_float(c); r.v[3] = __uint_as_float(d);
    r.v[4] = __uint_as_float(e); r.v[5] = __uint_as_float(f);
    r.v[6] = __uint_as_float(g); r.v[7] = __uint_as_float(h);
    return r;
}

// ---------------------------------------------------------------------------
// Persistent kernel, batch-sliced: 32 independent groups of 37 blocks run the
// full SE pipeline on their own batch element, with per-group barriers only.
// Groups drift freely -> one group's MLP/barrier overlaps another's DRAM
// streaming, so the memory pipe never drains (the R13 global-barrier flaw).
// ---------------------------------------------------------------------------
__global__ __launch_bounds__(256, 8) void se_fused_kernel(
    const float* __restrict__ x,
    const float* __restrict__ w1, const float* __restrict__ b1,
    const float* __restrict__ w2, const float* __restrict__ b2,
    float* __restrict__ out)
{
    const int tid  = threadIdx.x;
    const int warp = tid >> 5;
    const int lane = tid & 31;
    const int b    = blockIdx.x / GRP;        // batch element 0..31
    const int j    = blockIdx.x % GRP;        // block within group 0..36
    const int wg   = j * 8 + warp;            // warp within group 0..295

    // ---- Phase A: pool this batch's 768 rows (warp per row, evict-last) ----
    for (int r = wg; r < C; r += GW) {
        const int row = b * C + r;
        const float* p = x + (size_t)row * HW;    // 4096B row = 128 x 32B
        float acc = 0.0f;
#pragma unroll
        for (int i = 0; i < 4; ++i) {
            f8 v = ld_f8_evict_last(p + (lane + i * 32) * 8);
            acc += ((v.v[0] + v.v[1]) + (v.v[2] + v.v[3]))
                 + ((v.v[4] + v.v[5]) + (v.v[6] + v.v[7]));
        }
#pragma unroll
        for (int o = 16; o > 0; o >>= 1)
            acc += __shfl_xor_sync(0xffffffffu, acc, o);
        if (lane == 0)
            g_s[row] = acc * (1.0f / (float)HW);
    }
    batch_sync(b);

    // ---- Phase B: h[b,:] = swish(s[b,:] @ w1^T + b1)  (192 outputs) ----
    if (wg < CR) {
        const int jj = wg;
        const float4* wr = reinterpret_cast<const float4*>(w1 + (size_t)jj * C);
        const float4* sv = reinterpret_cast<const float4*>(g_s + (size_t)b * C);
        float a = 0.0f;
#pragma unroll
        for (int i = 0; i < 6; ++i) {             // 6*32 f4 = 768 floats
            float4 w = wr[lane + i * 32];
            float4 s = sv[lane + i * 32];
            a += w.x * s.x + w.y * s.y + w.z * s.z + w.w * s.w;
        }
#pragma unroll
        for (int off = 16; off > 0; off >>= 1)
            a += __shfl_xor_sync(0xffffffffu, a, off);
        if (lane == 0) {
            a += b1[jj];
            g_h[b * CR + jj] = a * (1.0f / (1.0f + __expf(-a)));   // swish
        }
    }
    batch_sync(b);

    // ---- Phase C: g[b,:] = sigmoid(h[b,:] @ w2^T + b2)  (768 outputs) ----
    for (int c = wg; c < C; c += GW) {
        const float2* wr = reinterpret_cast<const float2*>(w2 + (size_t)c * CR);
        const float2* hv = reinterpret_cast<const float2*>(g_h + (size_t)b * CR);
        float a = 0.0f;
#pragma unroll
        for (int i = 0; i < 3; ++i) {             // 3*32 f2 = 192 floats
            float2 w = wr[lane + i * 32];
            float2 h = hv[lane + i * 32];
            a += w.x * h.x + w.y * h.y;
        }
#pragma unroll
        for (int off = 16; off > 0; off >>= 1)
            a += __shfl_xor_sync(0xffffffffu, a, off);
        if (lane == 0)
            g_g[b * C + c] = 1.0f / (1.0f + __expf(-(a + b2[c])));
    }
    batch_sync(b);

    // ---- Phase D: scale this batch's rows. Block j handles a contiguous
    // DCHUNK-row span (~84KB stream). x reads hit the L2-pinned slice;
    // stores are evict-first (__stcs). 2 rows per iter for MLP=2. ----
    {
        const int r_beg = j * DCHUNK;
        const int r_end = (r_beg + DCHUNK < C) ? r_beg + DCHUNK : C;
        int r = r_beg;
        for (; r + 1 < r_end; r += 2) {
            const int row = b * C + r;
            const float4* xp = reinterpret_cast<const float4*>(x) + (size_t)row * 256;
            float4*       op = reinterpret_cast<float4*>(out)     + (size_t)row * 256;
            const float gv0 = g_g[row];
            const float gv1 = g_g[row + 1];
            float4 v0 = xp[tid];
            float4 v1 = xp[tid + 256];
            v0.x *= gv0; v0.y *= gv0; v0.z *= gv0; v0.w *= gv0;
            v1.x *= gv1; v1.y *= gv1; v1.z *= gv1; v1.w *= gv1;
            __stcs(op + tid,       v0);
            __stcs(op + tid + 256, v1);
        }
        if (r < r_end) {
            const int row = b * C + r;
            const float4* xp = reinterpret_cast<const float4*>(x) + (size_t)row * 256;
            float4*       op = reinterpret_cast<float4*>(out)     + (size_t)row * 256;
            const float gv = g_g[row];
            float4 v = xp[tid];
            v.x *= gv; v.y *= gv; v.z *= gv; v.w *= gv;
            __stcs(op + tid, v);
        }
    }
}

// ---------------------------------------------------------------------------
extern "C" void kernel_launch(void* const* d_in, const int* in_sizes, int n_in,
                              void* d_out, int out_size) {
    const float* x  = (const float*)d_in[0];   // [B, C, H, W]
    const float* w1 = (const float*)d_in[1];   // [Cr, C]
    const float* b1 = (const float*)d_in[2];   // [Cr]
    const float* w2 = (const float*)d_in[3];   // [C, Cr]
    const float* b2 = (const float*)d_in[4];   // [C]
    float* out = (float*)d_out;

    se_fused_kernel<<<NB, 256>>>(x, w1, b1, w2, b2, out);
}

// round 16
// speedup vs baseline: 1.6954x; 1.0163x over previous
#include <cuda_runtime.h>
#include <cuda_bf16.h>
#include <cstdint>

// Shapes (fixed per reference setup_inputs)
#define B   32
#define C   768
#define CR  192
#define HW  1024          // 32*32
#define ROWS (B * C)      // 24576 (b,c) rows of 1024 floats each

// Scratch (no device allocation allowed in kernel_launch)
__device__ float g_s[B * C];    // squeezed means   [B, C]
__device__ float g_h[B * CR];   // hidden (swish)   [B, Cr]

// 256-bit read-only load with L2 evict-last priority (ptxas/sm_103 requires
// .v8.b32 for .L2::evict_last). Pins x in L2 for the scale kernel's re-read.
struct f8 { float v[8]; };
__device__ __forceinline__ f8 ld_f8_evict_last(const void* p) {
    uint32_t a, b, c, d, e, f, g, h;
    asm("ld.global.nc.L2::evict_last.v8.b32 {%0,%1,%2,%3,%4,%5,%6,%7}, [%8];"
        : "=r"(a), "=r"(b), "=r"(c), "=r"(d),
          "=r"(e), "=r"(f), "=r"(g), "=r"(h) : "l"(p));
    f8 r;
    r.v[0] = __uint_as_float(a); r.v[1] = __uint_as_float(b);
    r.v[2] = __uint_as_float(c); r.v[3] = __uint_as_float(d);
    r.v[4] = __uint_as_float(e); r.v[5] = __uint_as_float(f);
    r.v[6] = __uint_as_float(g); r.v[7] = __uint_as_float(h);
    return r;
}

// ---------------------------------------------------------------------------
// Kernel 1: global average pool. One warp per (b,c) row of 1024 floats.
// 8 warps / block of 256 threads. Each lane: 4x 32-byte evict-last loads.
// Pins x (100.7MB) into the ~126MB L2 with evict-last priority.
// ---------------------------------------------------------------------------
__global__ __launch_bounds__(256) void se_pool_kernel(const float* __restrict__ x) {
    const int warp = threadIdx.x >> 5;
    const int lane = threadIdx.x & 31;
    const int row  = blockIdx.x * 8 + warp;          // < ROWS by grid sizing
    const float* p = x + (size_t)row * HW;           // 4096B row = 128x 32B

    float acc = 0.0f;
#pragma unroll
    for (int i = 0; i < 4; ++i) {
        f8 v = ld_f8_evict_last(p + (lane + i * 32) * 8);
        acc += ((v.v[0] + v.v[1]) + (v.v[2] + v.v[3]))
             + ((v.v[4] + v.v[5]) + (v.v[6] + v.v[7]));
    }
#pragma unroll
    for (int o = 16; o > 0; o >>= 1)
        acc += __shfl_xor_sync(0xffffffffu, acc, o);

    if (lane == 0)
        g_s[row] = acc * (1.0f / (float)HW);
}

// ---------------------------------------------------------------------------
// Kernel 2: h = swish(s @ w1^T + b1), [B, Cr] = 6144 outputs, warp each.
// PDL secondary: launched programmatically under the pool; waits on the grid
// dependency before reading g_s.
// ---------------------------------------------------------------------------
__global__ __launch_bounds__(256) void se_mlp1_kernel(const float* __restrict__ w1,
                                                      const float* __restrict__ b1) {
    cudaGridDependencySynchronize();        // pool grid complete + visible

    const int warp = threadIdx.x >> 5;
    const int lane = threadIdx.x & 31;
    const int out  = blockIdx.x * 8 + warp;     // < B*CR
    const int b    = out / CR;
    const int j    = out % CR;

    const float4* wr = reinterpret_cast<const float4*>(w1 + (size_t)j * C);
    const float4* sv = reinterpret_cast<const float4*>(g_s + (size_t)b * C);

    float a = 0.0f;
#pragma unroll
    for (int i = 0; i < 6; ++i) {               // 6*32 = 192 f4 = 768 floats
        float4 w = wr[lane + i * 32];
        float4 s = sv[lane + i * 32];
        a += w.x * s.x + w.y * s.y + w.z * s.z + w.w * s.w;
    }
#pragma unroll
    for (int o = 16; o > 0; o >>= 1)
        a += __shfl_xor_sync(0xffffffffu, a, o);

    if (lane == 0) {
        a += b1[j];
        g_h[out] = a * (1.0f / (1.0f + __expf(-a)));   // swish
    }
}

// ---------------------------------------------------------------------------
// Kernel 3: fused gate + scale (PDL secondary under mlp1). Block = 4 rows of
// one batch element: stage h[b,:] in smem, warps 0..3 compute the 4 gates
// (w2 is L2-hot), then all 256 threads stream-scale 4 rows (MLP=4).
// Stores are __stcs (evict-first) so the output stream does not evict the
// evict-last-pinned x.
// ---------------------------------------------------------------------------
__global__ __launch_bounds__(256) void se_scale_kernel(const float* __restrict__ x,
                                                       const float* __restrict__ w2,
                                                       const float* __restrict__ b2,
                                                       float* __restrict__ out) {
    cudaGridDependencySynchronize();        // mlp1 grid complete + visible

    __shared__ float hh[CR];
    __shared__ float gs[4];

    const int r0   = blockIdx.x * 4;            // 4 rows, all within one b
    const int b    = r0 / C;
    const int c0   = r0 % C;
    const int t    = threadIdx.x;
    const int warp = t >> 5;
    const int lane = t & 31;

    if (t < CR) hh[t] = g_h[b * CR + t];
    __syncthreads();

    if (warp < 4) {
        const int c = c0 + warp;
        const float2* wr = reinterpret_cast<const float2*>(w2 + (size_t)c * CR);
        const float2* hv = reinterpret_cast<const float2*>(hh);
        float a = 0.0f;
#pragma unroll
        for (int i = 0; i < 3; ++i) {           // 3*32 f2 = 192 floats
            float2 w = wr[lane + i * 32];
            float2 h = hv[lane + i * 32];
            a += w.x * h.x + w.y * h.y;
        }
#pragma unroll
        for (int o = 16; o > 0; o >>= 1)
            a += __shfl_xor_sync(0xffffffffu, a, o);
        if (lane == 0)
            gs[warp] = 1.0f / (1.0f + __expf(-(a + b2[c])));
    }
    __syncthreads();

    const float gv0 = gs[0], gv1 = gs[1], gv2 = gs[2], gv3 = gs[3];

    const float4* xp = reinterpret_cast<const float4*>(x) + (size_t)r0 * 256;
    float4*       op = reinterpret_cast<float4*>(out)     + (size_t)r0 * 256;

    float4 v0 = xp[t];
    float4 v1 = xp[t + 256];
    float4 v2 = xp[t + 512];
    float4 v3 = xp[t + 768];

    v0.x *= gv0; v0.y *= gv0; v0.z *= gv0; v0.w *= gv0;
    v1.x *= gv1; v1.y *= gv1; v1.z *= gv1; v1.w *= gv1;
    v2.x *= gv2; v2.y *= gv2; v2.z *= gv2; v2.w *= gv2;
    v3.x *= gv3; v3.y *= gv3; v3.z *= gv3; v3.w *= gv3;

    __stcs(op + t,       v0);
    __stcs(op + t + 256, v1);
    __stcs(op + t + 512, v2);
    __stcs(op + t + 768, v3);
}

// ---------------------------------------------------------------------------
// Launch: pool normally; mlp1 and scale as programmatic dependent launches so
// their GPU-side launch/dispatch overlaps the producer's tail instead of
// serializing after it (the ~14us of inter-node gap in the 3-kernel graph).
// ---------------------------------------------------------------------------
extern "C" void kernel_launch(void* const* d_in, const int* in_sizes, int n_in,
                              void* d_out, int out_size) {
    const float* x  = (const float*)d_in[0];   // [B, C, H, W]
    const float* w1 = (const float*)d_in[1];   // [Cr, C]
    const float* b1 = (const float*)d_in[2];   // [Cr]
    const float* w2 = (const float*)d_in[3];   // [C, Cr]
    const float* b2 = (const float*)d_in[4];   // [C]
    float* out = (float*)d_out;

    se_pool_kernel<<<ROWS / 8, 256>>>(x);

    cudaLaunchAttribute pdl;
    pdl.id = cudaLaunchAttributeProgrammaticStreamSerialization;
    pdl.val.programmaticStreamSerializationAllowed = 1;

    {
        cudaLaunchConfig_t cfg = {};
        cfg.gridDim  = dim3((B * CR) / 8);
        cfg.blockDim = dim3(256);
        cfg.stream   = 0;                    // same (legacy) stream as <<<>>>
        cfg.attrs    = &pdl;
        cfg.numAttrs = 1;
        cudaLaunchKernelEx(&cfg, se_mlp1_kernel, w1, b1);
    }
    {
        cudaLaunchConfig_t cfg = {};
        cfg.gridDim  = dim3(ROWS / 4);
        cfg.blockDim = dim3(256);
        cfg.stream   = 0;
        cfg.attrs    = &pdl;
        cfg.numAttrs = 1;
        cudaLaunchKernelEx(&cfg, se_scale_kernel, x, w2, b2, out);
    }
}